// round 3
// baseline (speedup 1.0000x reference)
#include <cuda_runtime.h>

// IntegrableMLP forward-mode Jacobian — f32x2-paired, LDS.128 weights.
// inputs [B,2], layers 2->32->32->16 (swish), out[b,n] = V . alpha2[b,n,:].
// Input order: inputs, W0, b0, W1, b1, W2, b2, V.  Output float32 [B,2].

#define H0 32
#define H1 32
#define H2 16
#define BLOCK 128

typedef unsigned long long ull;

struct __align__(16) Smem {
    float W1[H1 * H0];            // 4 KB, row-major, read as ulonglong2
    float W2[H2 * H1];            // 2 KB
    ull   nasp[(H1 / 2) * BLOCK]; // swish(z1) pairs   (16 KB)
    float2 W0p[H0];
    float b0[H0], b1[H1], b2[H2], V[H2];
    float d0s[H0 * BLOCK];        // dswish(z0)        (16 KB)
    float d1s[H1 * BLOCK];        // dswish(z1)        (16 KB)
};

__device__ __forceinline__ ull packf2(float lo, float hi) {
    ull r;
    asm("mov.b64 %0, {%1, %2};" : "=l"(r)
        : "r"(__float_as_uint(lo)), "r"(__float_as_uint(hi)));
    return r;
}
__device__ __forceinline__ void unpackf2(ull p, float& lo, float& hi) {
    unsigned a, b;
    asm("mov.b64 {%0, %1}, %2;" : "=r"(a), "=r"(b) : "l"(p));
    lo = __uint_as_float(a);
    hi = __uint_as_float(b);
}
__device__ __forceinline__ ull ffma2(ull a, ull b, ull c) {
    ull d;
    asm("fma.rn.f32x2 %0, %1, %2, %3;" : "=l"(d) : "l"(a), "l"(b), "l"(c));
    return d;
}
__device__ __forceinline__ float hadd2(ull p) {
    float lo, hi;
    unpackf2(p, lo, hi);
    return lo + hi;
}
__device__ __forceinline__ float fast_sigmoid(float z) {
    return 1.0f / (1.0f + __expf(-z));
}
// swish + derivative
__device__ __forceinline__ void swishd(float z, float& sw, float& d) {
    float s = fast_sigmoid(z);
    sw = z * s;
    d = fmaf(s, 1.0f - sw, sw);
}

__global__ __launch_bounds__(BLOCK, 4)
void integrable_mlp_kernel(
    const float2* __restrict__ x,
    const float* __restrict__ gW0, const float* __restrict__ gb0,
    const float* __restrict__ gW1, const float* __restrict__ gb1,
    const float* __restrict__ gW2, const float* __restrict__ gb2,
    const float* __restrict__ gV,
    float2* __restrict__ out, int B)
{
    extern __shared__ char smem_raw[];
    Smem& sm = *reinterpret_cast<Smem*>(smem_raw);
    const int tid = threadIdx.x;

    for (int j = tid; j < H1 * H0; j += BLOCK) sm.W1[j] = gW1[j];
    for (int j = tid; j < H2 * H1; j += BLOCK) sm.W2[j] = gW2[j];
    if (tid < H0) {
        sm.W0p[tid] = reinterpret_cast<const float2*>(gW0)[tid];
        sm.b0[tid] = gb0[tid];
        sm.b1[tid] = gb1[tid];
    }
    if (tid < H2) {
        sm.b2[tid] = gb2[tid];
        sm.V[tid] = gV[tid];
    }
    __syncthreads();

    const int idx = blockIdx.x * BLOCK + tid;
    if (idx >= B) return;
    const float2 xin = x[idx];

    const ulonglong2* __restrict__ W1v = reinterpret_cast<const ulonglong2*>(sm.W1);
    const ulonglong2* __restrict__ W2v = reinterpret_cast<const ulonglong2*>(sm.W2);

    // ---- Layer 0: 2 -> 32.  a packed into pairs; d0 to scratch.
    ull ap[H0 / 2];
#pragma unroll
    for (int j = 0; j < H0 / 2; j++) {
        float2 wA = sm.W0p[2 * j];
        float2 wB = sm.W0p[2 * j + 1];
        float zA = fmaf(wA.x, xin.x, fmaf(wA.y, xin.y, sm.b0[2 * j]));
        float zB = fmaf(wB.x, xin.x, fmaf(wB.y, xin.y, sm.b0[2 * j + 1]));
        float swA, dA, swB, dB;
        swishd(zA, swA, dA);
        swishd(zB, swB, dB);
        ap[j] = packf2(swA, swB);
        sm.d0s[(2 * j) * BLOCK + tid] = dA;
        sm.d0s[(2 * j + 1) * BLOCK + tid] = dB;
    }

    // ---- Layer 1 z-chain: 32 -> 32 (pairs of output rows per iteration).
#pragma unroll
    for (int op = 0; op < H1 / 2; op++) {
        ull zpA = 0ull, zpB = 0ull;
        const ulonglong2* rA = W1v + (2 * op) * (H0 / 4);
        const ulonglong2* rB = W1v + (2 * op + 1) * (H0 / 4);
#pragma unroll
        for (int j = 0; j < H0 / 4; j++) {
            ulonglong2 wA = rA[j];
            ulonglong2 wB = rB[j];
            zpA = ffma2(wA.x, ap[2 * j], zpA);
            zpA = ffma2(wA.y, ap[2 * j + 1], zpA);
            zpB = ffma2(wB.x, ap[2 * j], zpB);
            zpB = ffma2(wB.y, ap[2 * j + 1], zpB);
        }
        float zA = sm.b1[2 * op] + hadd2(zpA);
        float zB = sm.b1[2 * op + 1] + hadd2(zpB);
        float swA, dA, swB, dB;
        swishd(zA, swA, dA);
        swishd(zB, swB, dB);
        sm.nasp[op * BLOCK + tid] = packf2(swA, swB);
        sm.d1s[(2 * op) * BLOCK + tid] = dA;
        sm.d1s[(2 * op + 1) * BLOCK + tid] = dB;
    }

    // ---- Layer 1 Jacobian, two passes (input row 0, then row 1).
    ull n0p[H1 / 2], n1p[H1 / 2];
#pragma unroll
    for (int pass = 0; pass < 2; pass++) {
        // alp[j] = (d0_{2j} * W0[2j][pass], d0_{2j+1} * W0[2j+1][pass])
        ull alp[H0 / 2];
#pragma unroll
        for (int j = 0; j < H0 / 2; j++) {
            float dA = sm.d0s[(2 * j) * BLOCK + tid];
            float dB = sm.d0s[(2 * j + 1) * BLOCK + tid];
            float wA = pass ? sm.W0p[2 * j].y : sm.W0p[2 * j].x;
            float wB = pass ? sm.W0p[2 * j + 1].y : sm.W0p[2 * j + 1].x;
            alp[j] = packf2(dA * wA, dB * wB);
        }
#pragma unroll
        for (int op = 0; op < H1 / 2; op++) {
            ull tpA = 0ull, tpB = 0ull;
            const ulonglong2* rA = W1v + (2 * op) * (H0 / 4);
            const ulonglong2* rB = W1v + (2 * op + 1) * (H0 / 4);
#pragma unroll
            for (int j = 0; j < H0 / 4; j++) {
                ulonglong2 wA = rA[j];
                ulonglong2 wB = rB[j];
                tpA = ffma2(wA.x, alp[2 * j], tpA);
                tpA = ffma2(wA.y, alp[2 * j + 1], tpA);
                tpB = ffma2(wB.x, alp[2 * j], tpB);
                tpB = ffma2(wB.y, alp[2 * j + 1], tpB);
            }
            float nA = sm.d1s[(2 * op) * BLOCK + tid] * hadd2(tpA);
            float nB = sm.d1s[(2 * op + 1) * BLOCK + tid] * hadd2(tpB);
            if (pass == 0) n0p[op] = packf2(nA, nB);
            else           n1p[op] = packf2(nA, nB);
        }
    }

    // ---- Layer 2 (jammed): z + both Jacobian rows + V contraction.
    ull nap[H1 / 2];
#pragma unroll
    for (int j = 0; j < H1 / 2; j++) nap[j] = sm.nasp[j * BLOCK + tid];

    float out0 = 0.0f, out1 = 0.0f;
#pragma unroll
    for (int o = 0; o < H2; o++) {
        ull zp = 0ull, t0p = 0ull, t1p = 0ull;
        const ulonglong2* r = W2v + o * (H1 / 4);
#pragma unroll
        for (int j = 0; j < H1 / 4; j++) {
            ulonglong2 w = r[j];
            zp  = ffma2(w.x, nap[2 * j], zp);
            zp  = ffma2(w.y, nap[2 * j + 1], zp);
            t0p = ffma2(w.x, n0p[2 * j], t0p);
            t0p = ffma2(w.y, n0p[2 * j + 1], t0p);
            t1p = ffma2(w.x, n1p[2 * j], t1p);
            t1p = ffma2(w.y, n1p[2 * j + 1], t1p);
        }
        float z = sm.b2[o] + hadd2(zp);
        float sw, d;
        swishd(z, sw, d);
        float vd = sm.V[o] * d;
        out0 = fmaf(vd, hadd2(t0p), out0);
        out1 = fmaf(vd, hadd2(t1p), out1);
    }

    out[idx] = make_float2(out0, out1);
}

extern "C" void kernel_launch(void* const* d_in, const int* in_sizes, int n_in,
                              void* d_out, int out_size) {
    const float2* x = (const float2*)d_in[0];
    const float* W0 = (const float*)d_in[1];
    const float* b0 = (const float*)d_in[2];
    const float* W1 = (const float*)d_in[3];
    const float* b1 = (const float*)d_in[4];
    const float* W2 = (const float*)d_in[5];
    const float* b2 = (const float*)d_in[6];
    const float* V  = (const float*)d_in[7];
    float2* out = (float2*)d_out;

    int B = in_sizes[0] / 2;
    int blocks = (B + BLOCK - 1) / BLOCK;
    size_t shmem = sizeof(Smem);

    cudaFuncSetAttribute(integrable_mlp_kernel,
                         cudaFuncAttributeMaxDynamicSharedMemorySize,
                         (int)shmem);
    integrable_mlp_kernel<<<blocks, BLOCK, shmem>>>(
        x, W0, b0, W1, b1, W2, b2, V, out, B);
}